// round 15
// baseline (speedup 1.0000x reference)
#include <cuda_runtime.h>
#include <cuda_bf16.h>
#include <cstdint>

#define NN 256
#define LL 256
#define BB 16384

#if defined(__CUDA_ARCH_FEAT_SM103_ALL) || defined(__CUDA_ARCH_FEAT_SM100_ALL) || defined(__CUDA_ARCH_FEAT_SM101_ALL)
#define HAS_TC 1
#else
#define HAS_TC 0
#endif

typedef unsigned long long u64;

// ---------------- scratch ----------------
__device__ float4 g_C[LL * NN];   // packed coeffs (diag.x, diag.y, off.x, off.y)
__device__ __align__(128) __nv_bfloat16 g_Wrh[256 * 256];
__device__ __align__(128) __nv_bfloat16 g_Wrl[256 * 256];
__device__ __align__(128) __nv_bfloat16 g_Wih[256 * 256];
__device__ __align__(128) __nv_bfloat16 g_Wil[256 * 256];

// ---------------- common helpers ----------------
__device__ __forceinline__ uint32_t smem_u32(const void* p) {
    uint32_t a;
    asm("{ .reg .u64 t; cvta.to.shared.u64 t, %1; cvt.u32.u64 %0, t; }" : "=r"(a) : "l"(p));
    return a;
}
__device__ __forceinline__ float2 cmul(float2 a, float2 b) {
    return make_float2(a.x * b.x - a.y * b.y, a.x * b.y + a.y * b.x);
}
union BU { __nv_bfloat162 h; uint32_t u; };
union F2U { float2 f; u64 u; };

#define FMA_F32X2(d, a, b) \
    asm("fma.rn.f32x2 %0, %1, %2, %0;" : "+l"(d) : "l"(a), "l"(b))
#define MUL_F32X2(d, a, b) \
    asm("mul.rn.f32x2 %0, %1, %2;" : "=l"(d) : "l"(a), "l"(b))
__device__ __forceinline__ u64 pack2(float lo, float hi) {
    u64 r; asm("mov.b64 %0, {%1,%2};" : "=l"(r) : "f"(lo), "f"(hi)); return r;
}
__device__ __forceinline__ u64 dup2(float x) {
    u64 r; asm("mov.b64 %0, {%1,%1};" : "=l"(r) : "f"(x)); return r;
}
// complex step: y = v0*d + v1*o, d=(c.x,c.y), o=(c.z,c.w)
__device__ __forceinline__ float2 cfma4(float2 v0, float2 v1, float4 c) {
    u64 w;
    MUL_F32X2(w, dup2(v0.x), pack2(c.x, c.y));
    FMA_F32X2(w, dup2(v0.y), pack2(-c.y, c.x));
    FMA_F32X2(w, dup2(v1.x), pack2(c.z, c.w));
    FMA_F32X2(w, dup2(v1.y), pack2(-c.w, c.z));
    F2U cv; cv.u = w; return cv.f;
}

// ---------------- tcgen05 / async helpers (cg1) ----------------
#define TCGEN05_ALLOC(sa, n) \
    asm volatile("tcgen05.alloc.cta_group::1.sync.aligned.shared::cta.b32 [%0], %1;" :: "r"((uint32_t)(sa)), "r"((uint32_t)(n)) : "memory")
#define TCGEN05_DEALLOC(t, n) \
    asm volatile("tcgen05.dealloc.cta_group::1.sync.aligned.b32 %0, %1;" :: "r"(t), "r"((uint32_t)(n)))
#define TCGEN05_RELINQ() \
    asm volatile("tcgen05.relinquish_alloc_permit.cta_group::1.sync.aligned;")
#define TCGEN05_COMMIT(mb) \
    asm volatile("tcgen05.commit.cta_group::1.mbarrier::arrive::one.shared::cluster.b64 [%0];" :: "r"((uint32_t)(mb)) : "memory")
#define TCGEN05_WAIT_LD() asm volatile("tcgen05.wait::ld.sync.aligned;" ::: "memory")
#define TCGEN05_FENCE_AFTER() asm volatile("tcgen05.fence::after_thread_sync;" ::: "memory")
#define FENCE_ASYNC_SHARED() asm volatile("fence.proxy.async.shared::cta;" ::: "memory")

#define MBARRIER_INIT(mb, cnt) \
    asm volatile("mbarrier.init.shared.b64 [%0], %1;" :: "r"((uint32_t)(mb)), "r"((uint32_t)(cnt)) : "memory")
#define MBARRIER_ARRIVE(mb) \
    asm volatile("mbarrier.arrive.shared.b64 _, [%0];" :: "r"((uint32_t)(mb)) : "memory")
#define MBARRIER_EXPECT_TX(mb, tx) \
    asm volatile("mbarrier.arrive.expect_tx.shared.b64 _, [%0], %1;" :: "r"((uint32_t)(mb)), "r"((uint32_t)(tx)) : "memory")
#define MBARRIER_WAIT_PARITY(mb, ph) do { \
    uint32_t _mb = (uint32_t)(mb), _ph = (uint32_t)(ph), _done; \
    asm volatile("{\n\t.reg .pred p;\n\tmbarrier.try_wait.parity.acquire.cta.shared::cta.b64 p, [%1], %2;\n\tselp.b32 %0, 1, 0, p;\n\t}" \
        : "=r"(_done) : "r"(_mb), "r"(_ph) : "memory"); \
    if (!_done) { \
        asm volatile("{\n\t.reg .pred P1;\n\tWL_%=:\n\tmbarrier.try_wait.parity.acquire.cta.shared::cta.b64 P1, [%0], %1, 0x989680;\n\t@P1 bra.uni WD_%=;\n\tbra.uni WL_%=;\n\tWD_%=:\n\t}" \
            :: "r"(_mb), "r"(_ph) : "memory"); \
    } } while (0)

#define CP_ASYNC_BULK(dst, src, bytes, mb) \
    asm volatile("cp.async.bulk.shared::cluster.global.mbarrier::complete_tx::bytes [%0], [%1], %2, [%3];" \
        :: "r"((uint32_t)(dst)), "l"(src), "r"((uint32_t)(bytes)), "r"((uint32_t)(mb)) : "memory")

#define TCGEN05_LD_32X32B_X32(r, ta) \
    asm volatile("tcgen05.ld.sync.aligned.32x32b.x32.b32 " \
        "{%0,%1,%2,%3,%4,%5,%6,%7,%8,%9,%10,%11,%12,%13,%14,%15," \
        "%16,%17,%18,%19,%20,%21,%22,%23,%24,%25,%26,%27,%28,%29,%30,%31}, [%32];" \
        : "=r"((r)[0]), "=r"((r)[1]), "=r"((r)[2]), "=r"((r)[3]), "=r"((r)[4]), "=r"((r)[5]), "=r"((r)[6]), "=r"((r)[7]), \
          "=r"((r)[8]), "=r"((r)[9]), "=r"((r)[10]), "=r"((r)[11]), "=r"((r)[12]), "=r"((r)[13]), "=r"((r)[14]), "=r"((r)[15]), \
          "=r"((r)[16]), "=r"((r)[17]), "=r"((r)[18]), "=r"((r)[19]), "=r"((r)[20]), "=r"((r)[21]), "=r"((r)[22]), "=r"((r)[23]), \
          "=r"((r)[24]), "=r"((r)[25]), "=r"((r)[26]), "=r"((r)[27]), "=r"((r)[28]), "=r"((r)[29]), "=r"((r)[30]), "=r"((r)[31]) \
        : "r"(ta))

#define SWZ64(o) ((o) ^ (((o) >> 3) & 0x30))

#if HAS_TC
__device__ __forceinline__ uint32_t elect_one_pred() {
    uint32_t p;
    asm volatile("{\n\t.reg .pred p;\n\telect.sync _|p, 0xFFFFFFFF;\n\tselp.b32 %0, 1, 0, p;\n\t}" : "=r"(p));
    return p;
}
__device__ __forceinline__ uint64_t make_desc_sw64(uint32_t base) {
    return ((uint64_t)4 << 61) | ((uint64_t)1 << 46) | ((uint64_t)32 << 32) | ((uint64_t)1 << 16)
         | (uint64_t)((base >> 4) & 0x3FFF);
}
__device__ __forceinline__ void mma_f16_ss_cg1(uint32_t d, uint64_t ad, uint64_t bd,
                                               uint32_t idesc, uint32_t en) {
    asm volatile(
        "{\n\t.reg .pred p;\n\tsetp.ne.u32 p, %5, 0;\n\t"
        "tcgen05.mma.cta_group::1.kind::f16 [%0], %1, %2, %3, {%4,%4,%4,%4}, p;\n\t}"
        :: "r"(d), "l"(ad), "l"(bd), "r"(idesc), "r"(0u), "r"(en) : "memory");
}
#endif

// ---------------- kernel 1: per-layer MZI coefficients ----------------
__global__ void coeff_kernel(const float* __restrict__ theta,
                             const float* __restrict__ phi) {
    __shared__ float2 ips[NN];
    __shared__ float2 eps[NN];
    __shared__ float2 offs[NN];
    int l = blockIdx.x;
    int n = threadIdx.x;
    const float* th = theta + l * (NN / 2);
    const float* ph = phi + l * (NN / 2);

    {
        float ang = 0.5f * th[n >> 1];
        if (n & 1) ang = -ang;
        float s, c; sincosf(ang, &s, &c);
        ips[n] = make_float2(c, s);
        if (n & 1) eps[n] = make_float2(1.f, 0.f);
        else { float s2, c2; sincosf(ph[n >> 1], &s2, &c2); eps[n] = make_float2(c2, s2); }
    }
    __syncthreads();

    int nm = (n - 1) & (NN - 1), np = (n + 1) & (NN - 1);
    float2 p0 = ips[nm], p1 = ips[n], p2 = ips[np];
    float2 v = make_float2(2.f * p1.x - p2.x - p0.x, 2.f * p1.y - p2.y - p0.y);
    float2 u = make_float2(2.f * p1.x + p2.x + p0.x, 2.f * p1.y + p2.y + p0.y);
    float2 en = eps[n], ep = eps[nm];

    float2 diag = cmul(en, v); diag.x *= 0.25f; diag.y *= 0.25f;
    float2 iu = make_float2(-u.y, u.x);
    float2 off = cmul(ep, iu); off.x *= 0.25f; off.y *= 0.25f;

    offs[n ^ 1] = off;
    __syncthreads();
    float2 o = offs[n];
    g_C[l * NN + n] = make_float4(diag.x, diag.y, o.x, o.y);
}

// ---------------- kernel 2: compose W — fused layer pairs, RB=1, 256 CTAs (R13) ----
__global__ __launch_bounds__(NN) void build_w_kernel(const float* __restrict__ gamma) {
    __shared__ float2 bufA[NN];
    __shared__ float2 bufB[NN];
    int i = threadIdx.x;
    int j0 = blockIdx.x;
    const int M = NN - 1;
    int odd = i & 1;

    {
        float2 v = make_float2(0.f, 0.f);
        if (i == j0) { float s, c; sincosf(gamma[j0], &s, &c); v = make_float2(c, s); }
        bufA[i] = v;
    }

    int xa1 = odd ? (i + 1) & M : (i - 1) & M;
    int xb0 = odd ? (i - 1) & M : (i + 1) & M;
    int xb1 = odd ? (i - 2) & M : (i + 2) & M;
    int ca = (i - 1) & M;
    int cb = odd ? (i - 2) & M : i;

    float4 c0 = g_C[i];
    float4 cL = g_C[255 * NN + i];

    float4 qa[2], qb[2], q2[2];
#pragma unroll
    for (int p = 0; p < 2; p++) {
        qa[p] = g_C[(2 * p + 1) * NN + ca];
        qb[p] = g_C[(2 * p + 1) * NN + cb];
        q2[p] = g_C[(2 * p + 2) * NN + i];
    }
    __syncthreads();

    float2* A = bufA;
    float2* Bx = bufB;

    Bx[i] = cfma4(A[i], A[i ^ 1], c0);
    __syncthreads();
    { float2* t_ = A; A = Bx; Bx = t_; }

    for (int p = 0; p < 127; ++p) {
        int sl = p & 1;
        float4 a4 = qa[sl], b4 = qb[sl], d4 = q2[sl];
        if (p + 2 < 127) {
            int pp = p + 2;
            qa[sl] = g_C[(2 * pp + 1) * NN + ca];
            qb[sl] = g_C[(2 * pp + 1) * NN + cb];
            q2[sl] = g_C[(2 * pp + 2) * NN + i];
        }
        float2 ma = cfma4(A[i], A[xa1], a4);
        float2 mb = cfma4(A[xb0], A[xb1], b4);
        Bx[i] = cfma4(ma, mb, d4);
        __syncthreads();
        float2* t_ = A; A = Bx; Bx = t_;
    }

    {
        int ia = (i + 1) & M;
        int ib = ((i ^ 1) + 1) & M;
        Bx[i] = cfma4(A[ia], A[ib], cL);
        __syncthreads();
        float2* t_ = A; A = Bx; Bx = t_;
    }

    auto store_b = [](__nv_bfloat16* img, int n, int k, __nv_bfloat16 v) {
        uint32_t off = ((uint32_t)k >> 5) * 16384u + SWZ64((uint32_t)(n * 64 + (k & 31) * 2));
        *(__nv_bfloat16*)((char*)img + off) = v;
    };

    int src = (i - 1) & M;
    {
        float2 w = A[src];
        int k = j0, n = i;
        __nv_bfloat16 hr = __float2bfloat16(w.x);
        __nv_bfloat16 lr = __float2bfloat16(w.x - __bfloat162float(hr));
        __nv_bfloat16 hi = __float2bfloat16(w.y);
        __nv_bfloat16 li = __float2bfloat16(w.y - __bfloat162float(hi));
        store_b(g_Wrh, n, k, hr);
        store_b(g_Wrl, n, k, lr);
        store_b(g_Wih, n, k, hi);
        store_b(g_Wil, n, k, li);
    }
}

// ---------------- kernel 3: cg1 GEMM, M128 x N128-half, 2 CTAs/SM ----------------
// CTA = (m-block, n-half). D in TMEM: Yr cols 0-127, Yi cols 128-255 (256 cols/CTA
// -> two CTAs share the SM's 512 TMEM cols). A double-buffered, W single-buffered.
// FIX vs R14: alloc and relinquish are SEQUENTIAL in warp 4 (relinquish racing
// ahead of alloc in another warp invalidates the alloc -> launch failure).
#define KC 32
#define SMEM_TMEM 0
#define MB_FULL(s)  (16 + (s) * 8)   // 4 A-warp arrivals + W expect_tx
#define MB_EMPTY(s) (32 + (s) * 8)   // commit of stage with slot s
#define MB_DONE     48
#define A_BASE(s)   (1024 + (s) * 32768)
#define XR_H 0
#define XR_L 8192
#define XI_H 16384
#define XI_L 24576
#define W_BASE      (1024 + 65536)
#define WR_H 0
#define WR_L 8192
#define WI_H 16384
#define WI_L 24576
#define SMEM_TOTAL  (1024 + 2 * 32768 + 32768)

__global__ __launch_bounds__(256, 2)
void gemm_tc_kernel(const float* __restrict__ xre, const float* __restrict__ xim,
                    float* __restrict__ out) {
#if HAS_TC
    extern __shared__ char smem[];
    const uint32_t sb = smem_u32(smem);
    int tid = threadIdx.x, wid = tid >> 5, lane = tid & 31;
    int m0 = blockIdx.x * 128;
    int nh = blockIdx.y;                 // n-half: cols nh*128 .. nh*128+127

    if (wid == 4) {
        TCGEN05_ALLOC(sb + SMEM_TMEM, 256);
        TCGEN05_RELINQ();                // sequential: permit released AFTER alloc
    }
    if (tid == 0) {
        MBARRIER_INIT(sb + MB_FULL(0), 5);
        MBARRIER_INIT(sb + MB_FULL(1), 5);
        MBARRIER_INIT(sb + MB_EMPTY(0), 1);
        MBARRIER_INIT(sb + MB_EMPTY(1), 1);
        MBARRIER_INIT(sb + MB_DONE, 1);
    }
    __syncthreads();
    uint32_t tmem;
    asm volatile("ld.shared.b32 %0, [%1];" : "=r"(tmem) : "r"(sb + SMEM_TMEM));

    if (wid < 4) {
        // ---- A producer (4 warps): fp32 -> bf16 hi/lo; sibling CTA hides LDG latency
        for (int it = 0; it < 8; ++it) {
            int s = it & 1;
            if (it >= 2) MBARRIER_WAIT_PARITY(sb + MB_EMPTY(s), ((it >> 1) - 1) & 1);
            uint32_t base = sb + A_BASE(s);
            int kc = it * KC;
#pragma unroll
            for (int j = 0; j < 16; ++j) {
                int pl = j >> 3;
                int g = (j & 7) * 128 + tid;
                int rr = g >> 3, f4 = g & 7;
                const float* plane = pl ? xim : xre;
                float4 v = *(const float4*)(plane + (size_t)(m0 + rr) * NN + kc + f4 * 4);
                BU h0, h1, l0, l1;
                h0.h = __floats2bfloat162_rn(v.x, v.y);
                h1.h = __floats2bfloat162_rn(v.z, v.w);
                float2 f0 = __bfloat1622float2(h0.h), f1 = __bfloat1622float2(h1.h);
                l0.h = __floats2bfloat162_rn(v.x - f0.x, v.y - f0.y);
                l1.h = __floats2bfloat162_rn(v.z - f1.x, v.w - f1.y);
                uint32_t off = SWZ64((uint32_t)(rr * 64 + f4 * 8));
                uint32_t hdst = base + (pl ? XI_H : XR_H) + off;
                uint32_t ldst = base + (pl ? XI_L : XR_L) + off;
                asm volatile("st.shared.v2.b32 [%0], {%1,%2};" :: "r"(hdst), "r"(h0.u), "r"(h1.u) : "memory");
                asm volatile("st.shared.v2.b32 [%0], {%1,%2};" :: "r"(ldst), "r"(l0.u), "r"(l1.u) : "memory");
            }
            FENCE_ASYNC_SHARED();
            __syncwarp();
            if (lane == 0) MBARRIER_ARRIVE(sb + MB_FULL(s));
        }
    } else if (wid == 5) {
        // ---- W producer (single buffer): refill gated by previous stage's commit
        size_t nslice = (size_t)nh * 8192;
        for (int it = 0; it < 8; ++it) {
            if (it >= 1) MBARRIER_WAIT_PARITY(sb + MB_EMPTY((it - 1) & 1), ((it - 1) >> 1) & 1);
            if (elect_one_pred()) {
                uint32_t mb = sb + MB_FULL(it & 1);
                size_t co = (size_t)it * 16384 + nslice;
                MBARRIER_EXPECT_TX(mb, 32768);
                CP_ASYNC_BULK(sb + W_BASE + WR_H, (const char*)g_Wrh + co, 8192, mb);
                CP_ASYNC_BULK(sb + W_BASE + WR_L, (const char*)g_Wrl + co, 8192, mb);
                CP_ASYNC_BULK(sb + W_BASE + WI_H, (const char*)g_Wih + co, 8192, mb);
                CP_ASYNC_BULK(sb + W_BASE + WI_L, (const char*)g_Wil + co, 8192, mb);
            }
        }
    } else if (wid == 4) {
        // ---- MMA warp: interleaved Yr/Yi chains, M128 N128 K16 dispatches
        const uint32_t IDESC = (1u << 4) | (1u << 7) | (1u << 10) | (16u << 17) | (8u << 24);
        const uint32_t NEG_A = 1u << 13;
        const uint32_t aoffs[6] = {XR_H, XR_L, XR_H, XI_H, XI_L, XI_H};
        const uint32_t boffr[6] = {WR_H, WR_H, WR_L, WI_H, WI_H, WI_L};   // Yr (g>=3: neg A)
        const uint32_t boffi[6] = {WI_H, WI_H, WI_L, WR_H, WR_H, WR_L};   // Yi
        uint64_t da[2] = { make_desc_sw64(sb + A_BASE(0)), make_desc_sw64(sb + A_BASE(1)) };
        uint64_t dw = make_desc_sw64(sb + W_BASE);
        for (int it = 0; it < 8; ++it) {
            int s = it & 1;
            MBARRIER_WAIT_PARITY(sb + MB_FULL(s), (it >> 1) & 1);
            if (elect_one_pred()) {
                uint64_t db = da[s];
#pragma unroll
                for (int g = 0; g < 6; ++g) {
                    uint32_t idr = IDESC | ((g >= 3) ? NEG_A : 0u);
#pragma unroll
                    for (int kk = 0; kk < 2; ++kk) {
                        uint64_t ad = db + (aoffs[g] >> 4) + kk * 2;
                        uint32_t en = !(it == 0 && g == 0 && kk == 0);
                        mma_f16_ss_cg1(tmem,       ad, dw + (boffr[g] >> 4) + kk * 2, idr,   en);
                        mma_f16_ss_cg1(tmem + 128, ad, dw + (boffi[g] >> 4) + kk * 2, IDESC, en);
                    }
                }
                TCGEN05_COMMIT((it == 7) ? (sb + MB_DONE) : (sb + MB_EMPTY(s)));
            }
        }
    }
    // warps 6,7: fall through to epilogue wait

    // ---- epilogue: WG0 -> Yr (re plane), WG1 -> Yi (im plane); 128 cols each
    MBARRIER_WAIT_PARITY(sb + MB_DONE, 0);
    TCGEN05_FENCE_AFTER();
    {
        int wg = tid >> 7;
        int wt = tid & 127;
        int m = m0 + wt;
        float* dst = out + (size_t)wg * BB * NN + (size_t)m * NN + nh * 128;
        uint32_t colbase = tmem + wg * 128;
#pragma unroll
        for (int c = 0; c < 4; ++c) {
            uint32_t r[32];
            TCGEN05_LD_32X32B_X32(r, colbase + c * 32);
            TCGEN05_WAIT_LD();
            float4* d4 = (float4*)(dst + c * 32);
#pragma unroll
            for (int q = 0; q < 8; ++q)
                d4[q] = make_float4(__uint_as_float(r[4 * q]), __uint_as_float(r[4 * q + 1]),
                                    __uint_as_float(r[4 * q + 2]), __uint_as_float(r[4 * q + 3]));
        }
    }
    __syncthreads();
    if (wid == 4) TCGEN05_DEALLOC(tmem, 256);
#endif  // HAS_TC
}

// ---------------- launch ----------------
extern "C" void kernel_launch(void* const* d_in, const int* in_sizes, int n_in,
                              void* d_out, int out_size) {
    const float* x_re  = (const float*)d_in[0];
    const float* x_im  = (const float*)d_in[1];
    const float* theta = (const float*)d_in[2];
    const float* phi   = (const float*)d_in[3];
    const float* gamma = (const float*)d_in[4];
    float* out = (float*)d_out;

    cudaFuncSetAttribute(gemm_tc_kernel, cudaFuncAttributeMaxDynamicSharedMemorySize, SMEM_TOTAL);

    coeff_kernel<<<LL, NN>>>(theta, phi);
    build_w_kernel<<<NN, NN>>>(gamma);
    dim3 grid(BB / 128, 2);
    gemm_tc_kernel<<<grid, 256, SMEM_TOTAL>>>(x_re, x_im, out);
}